// round 12
// baseline (speedup 1.0000x reference)
#include <cuda_runtime.h>
#include <math.h>
#include <stdint.h>

// ---------------------------------------------------------------------------
// ViT-Base forward: B=32, S=197, E=768, H=12, D=64, FC=3072, L=12
// Round 11: f32x2 GEMM with instruction-diet mainloop:
//   - A stored DUPLICATED in smem (f32x2 pairs ready; no pack2 movs)
//   - B fragments via LDS.128
//   - split-K reverted (proven overhead); merged QKV kept
//   - f32x2 packed math in attention QK^T and AV loops
// ---------------------------------------------------------------------------

#define BATCH 32
#define SEQ   197
#define EMB   768
#define HEADS 12
#define HDIM  64
#define FFN   3072
#define LAYERS 12
#define NPATCH 196
#define ROWS  (BATCH * SEQ)      // 6304
#define PROWS (BATCH * NPATCH)   // 6272

// Scratch
__device__ float g_x  [ROWS * EMB];
__device__ float g_q  [ROWS * EMB];
__device__ float g_k  [ROWS * EMB];
__device__ float g_v  [ROWS * EMB];
__device__ float g_o  [ROWS * EMB];
__device__ float g_t2 [ROWS * EMB];
__device__ float g_t1 [ROWS * FFN];
__device__ float g_pos[SEQ * EMB];

// ---------------------------------------------------------------------------
// Packed f32x2 helpers
// ---------------------------------------------------------------------------
__device__ __forceinline__ void fma2(unsigned long long& acc, unsigned long long a,
                                     unsigned long long b) {
    asm("fma.rn.f32x2 %0, %1, %2, %0;" : "+l"(acc) : "l"(a), "l"(b));
}
__device__ __forceinline__ unsigned long long pack2(float x) {
    unsigned long long r;
    asm("mov.b64 %0, {%1, %1};" : "=l"(r) : "f"(x));
    return r;
}
__device__ __forceinline__ float2 unpack2(unsigned long long v) {
    float2 f;
    asm("mov.b64 {%0, %1}, %2;" : "=f"(f.x), "=f"(f.y) : "l"(v));
    return f;
}
__device__ __forceinline__ float gelu(float v) {
    return 0.5f * v * (1.f + erff(v * 0.70710678118654752f));
}

// ---------------------------------------------------------------------------
// Patchify / pos / assemble
// ---------------------------------------------------------------------------
__global__ void patchify_kernel(const float* __restrict__ img, float* __restrict__ out) {
    int idx = blockIdx.x * 256 + threadIdx.x;
    if (idx >= PROWS * EMB) return;
    int col = idx % EMB;
    int row = idx / EMB;
    int b = row / NPATCH, p = row % NPATCH;
    int hh = p / 14, ww = p % 14;
    int c = col % 3;
    int pp = col / 3;
    int p1 = pp / 16, p2 = pp % 16;
    out[idx] = img[((b * 3 + c) * 224 + hh * 16 + p1) * 224 + ww * 16 + p2];
}

__global__ void pos_kernel(float* __restrict__ pos) {
    int idx = blockIdx.x * 256 + threadIdx.x;
    if (idx >= SEQ * EMB) return;
    int t = idx / EMB, j = idx % EMB;
    float val = 0.f;
    if (t > 0) {
        int tok = t - 1;
        int quad = j / 192;
        int i = j % 192;
        float omega = expf(-((float)i / 191.f) * logf(10000.f));
        float coord = (quad < 2) ? (float)(tok % 14) : (float)(tok / 14);
        float arg = coord * omega;
        val = (quad & 1) ? cosf(arg) : sinf(arg);
    }
    pos[idx] = val;
}

__global__ void assemble_kernel(const float* __restrict__ emb, const float* __restrict__ cls,
                                const float* __restrict__ pos, float* __restrict__ x) {
    int idx = blockIdx.x * 256 + threadIdx.x;
    if (idx >= ROWS * EMB) return;
    int e = idx % EMB;
    int bs = idx / EMB;
    int s = bs % SEQ, b = bs / SEQ;
    float val;
    if (s == 0) val = cls[e];
    else        val = emb[(b * NPATCH + s - 1) * EMB + e] + pos[s * EMB + e];
    x[idx] = val;
}

// ---------------------------------------------------------------------------
// f32x2 GEMM core (128x128x16 tile, 256 threads, 8x8 microtile).
// A staged DUPLICATED in smem: as[k][2m] = as[k][2m+1] = A[m][k], so the
// mainloop loads ready-packed f32x2 pairs (no movs). B fragments via LDS.128.
// ---------------------------------------------------------------------------
#define BM 128
#define BN 128
#define BK 16
#define A_STG 4096                 // 16 k-rows x 256 (duplicated) floats
#define B_STG 2048                 // 16 k-rows x 128 floats
#define STG   (A_STG + B_STG)      // 6144 floats per stage; 2 stages = 48 KB

__device__ __forceinline__ void gemm_core(
    const float* __restrict__ Ab, int lda,
    const float* __restrict__ Bb, int ldb,
    int Kiter, const float* __restrict__ bias,
    float* __restrict__ Cb, int ldc, int mrem, int act, float* sm)
{
    int tid = threadIdx.x;
    int tx = tid & 15, ty = tid >> 4;

    int ar[2], ac[2], br[2], bc[2];
    float4 pa[2], pb[2];
    #pragma unroll
    for (int i = 0; i < 2; i++) {
        int c = tid + i * 256;
        ar[i] = c >> 2;  ac[i] = (c & 3) * 4;
        br[i] = c >> 5;  bc[i] = (c & 31) * 4;
    }

    auto ldg = [&](int k0) {
        #pragma unroll
        for (int i = 0; i < 2; i++) {
            if (ar[i] < mrem)
                pa[i] = *(const float4*)(Ab + (size_t)ar[i] * lda + k0 + ac[i]);
            else
                pa[i] = make_float4(0.f, 0.f, 0.f, 0.f);
            pb[i] = *(const float4*)(Bb + (size_t)(k0 + br[i]) * ldb + bc[i]);
        }
    };
    auto sts = [&](int s) {
        float* as = sm + s * STG;
        float* bs = as + A_STG;
        #pragma unroll
        for (int i = 0; i < 2; i++) {
            int m2 = 2 * ar[i];
            float* a0 = as + (ac[i] + 0) * 256 + m2;
            float* a1 = as + (ac[i] + 1) * 256 + m2;
            float* a2 = as + (ac[i] + 2) * 256 + m2;
            float* a3 = as + (ac[i] + 3) * 256 + m2;
            a0[0] = pa[i].x; a0[1] = pa[i].x;
            a1[0] = pa[i].y; a1[1] = pa[i].y;
            a2[0] = pa[i].z; a2[1] = pa[i].z;
            a3[0] = pa[i].w; a3[1] = pa[i].w;
            *(float4*)(bs + br[i] * 128 + bc[i]) = pb[i];
        }
    };

    unsigned long long acc[8][4];
    #pragma unroll
    for (int i = 0; i < 8; i++)
        #pragma unroll
        for (int j = 0; j < 4; j++) acc[i][j] = 0ull;

    ldg(0); sts(0); __syncthreads();
    int nk = Kiter / BK;
    for (int kt = 0; kt < nk; kt++) {
        if (kt + 1 < nk) ldg((kt + 1) * BK);
        const float* as = sm + (kt & 1) * STG;
        const float* bs = as + A_STG;
        #pragma unroll
        for (int k = 0; k < BK; k++) {
            ulonglong2 a01 = *(const ulonglong2*)(as + k * 256 + ty * 8);
            ulonglong2 a23 = *(const ulonglong2*)(as + k * 256 + ty * 8 + 4);
            ulonglong2 a45 = *(const ulonglong2*)(as + k * 256 + ty * 8 + 128);
            ulonglong2 a67 = *(const ulonglong2*)(as + k * 256 + ty * 8 + 132);
            ulonglong2 b01 = *(const ulonglong2*)(bs + k * 128 + tx * 4);
            ulonglong2 b23 = *(const ulonglong2*)(bs + k * 128 + tx * 4 + 64);
            unsigned long long av[8] = {a01.x, a01.y, a23.x, a23.y,
                                        a45.x, a45.y, a67.x, a67.y};
            #pragma unroll
            for (int i = 0; i < 8; i++) {
                fma2(acc[i][0], av[i], b01.x);
                fma2(acc[i][1], av[i], b01.y);
                fma2(acc[i][2], av[i], b23.x);
                fma2(acc[i][3], av[i], b23.y);
            }
        }
        if (kt + 1 < nk) sts((kt + 1) & 1);
        __syncthreads();
    }

    #pragma unroll
    for (int i = 0; i < 8; i++) {
        int lr = ty * 4 + (i & 3) + (i >> 2) * 64;
        if (lr >= mrem) continue;
        float* crow = Cb + (size_t)lr * ldc;
        #pragma unroll
        for (int j = 0; j < 4; j++) {
            int lc = tx * 4 + (j & 1) * 2 + (j >> 1) * 64;
            float2 v = unpack2(acc[i][j]);
            if (bias) { v.x += bias[lc]; v.y += bias[lc + 1]; }
            if (act)  { v.x = gelu(v.x); v.y = gelu(v.y); }
            *(float2*)(crow + lc) = v;
        }
    }
}

// Standard GEMM: C[M,N] = A[M,K] @ B[K,N] (+bias)(+GELU)
__global__ __launch_bounds__(256, 2)
void gemm_kernel(const float* __restrict__ A, const float* __restrict__ B,
                 const float* __restrict__ bias, float* __restrict__ C,
                 int M, int N, int K, int act) {
    __shared__ float sm[2 * STG];
    int bm = blockIdx.y * BM, bn = blockIdx.x * BN;
    gemm_core(A + (size_t)bm * K, K, B + bn, N, K,
              bias ? bias + bn : nullptr,
              C + (size_t)bm * N + bn, N, M - bm, act, sm);
}

// Merged QKV GEMM: blockIdx.x selects which of Wq/Wk/Wv (6 N-tiles each)
__global__ __launch_bounds__(256, 2)
void qkv_kernel(const float* __restrict__ x,
                const float* __restrict__ Wq, const float* __restrict__ Wk,
                const float* __restrict__ Wv,
                float* __restrict__ q, float* __restrict__ k, float* __restrict__ v,
                int M) {
    __shared__ float sm[2 * STG];
    int sel = blockIdx.x / 6;
    int bn = (blockIdx.x % 6) * BN;
    const float* B = (sel == 0) ? Wq : (sel == 1) ? Wk : Wv;
    float* C = (sel == 0) ? q : (sel == 1) ? k : v;
    int bm = blockIdx.y * BM;
    gemm_core(x + (size_t)bm * EMB, EMB, B + bn, EMB, EMB,
              nullptr, C + (size_t)bm * EMB + bn, EMB, M - bm, 0, sm);
}

// ---------------------------------------------------------------------------
// Tiled attention with packed f32x2 inner loops.
// block = (16-query tile, head, batch). 256 threads.
// ---------------------------------------------------------------------------
#define QT   16
#define KSTR 68
#define LSTR 208
#define ATT_QS   (SEQ * KSTR)
#define ATT_LG   (ATT_QS + QT * KSTR)
#define ATT_INV  (ATT_LG + QT * LSTR)
#define ATT_SMEM ((ATT_INV + 16) * 4)

__global__ __launch_bounds__(256)
void attn_kernel(const float* __restrict__ q, const float* __restrict__ k,
                 const float* __restrict__ v, float* __restrict__ o) {
    extern __shared__ float sm[];
    float* Ks  = sm;
    float* Qs  = sm + ATT_QS;
    float* lg  = sm + ATT_LG;
    float* inv = sm + ATT_INV;
    int qt = blockIdx.x, h = blockIdx.y, b = blockIdx.z;
    int tid = threadIdx.x;
    const float scale = 0.125f;

    for (int idx = tid; idx < SEQ * 16; idx += 256) {
        int t = idx >> 4, d4 = (idx & 15) * 4;
        *(float4*)(Ks + t * KSTR + d4) =
            *(const float4*)(k + (size_t)(b * SEQ + t) * EMB + h * HDIM + d4);
    }
    {
        int t = tid >> 4, d4 = (tid & 15) * 4;
        int s = qt * QT + t;
        float4 qv = make_float4(0.f, 0.f, 0.f, 0.f);
        if (s < SEQ) qv = *(const float4*)(q + (size_t)(b * SEQ + s) * EMB + h * HDIM + d4);
        *(float4*)(Qs + t * KSTR + d4) = qv;
    }
    __syncthreads();

    // logits with f32x2 pair-dot
    int qq = tid >> 4, g = tid & 15;
    for (int pass = 0; pass < 13; pass++) {
        int t = g + pass * 16;
        if (t < SEQ) {
            unsigned long long accp = 0ull;
            #pragma unroll
            for (int d4 = 0; d4 < HDIM; d4 += 4) {
                ulonglong2 qp = *(const ulonglong2*)(Qs + qq * KSTR + d4);
                ulonglong2 kp = *(const ulonglong2*)(Ks + t * KSTR + d4);
                fma2(accp, qp.x, kp.x);
                fma2(accp, qp.y, kp.y);
            }
            float2 f = unpack2(accp);
            lg[qq * LSTR + t] = (f.x + f.y) * scale;
        }
    }
    __syncthreads();

    int warp = tid >> 5, lane = tid & 31;
    #pragma unroll
    for (int qi = warp * 2; qi < warp * 2 + 2; qi++) {
        float m = -1e30f;
        for (int t = lane; t < SEQ; t += 32) m = fmaxf(m, lg[qi * LSTR + t]);
        #pragma unroll
        for (int s = 16; s; s >>= 1) m = fmaxf(m, __shfl_xor_sync(0xFFFFFFFFu, m, s));
        float sum = 0.f;
        for (int t = lane; t < SEQ; t += 32) {
            float e = expf(lg[qi * LSTR + t] - m);
            lg[qi * LSTR + t] = e;
            sum += e;
        }
        #pragma unroll
        for (int s = 16; s; s >>= 1) sum += __shfl_xor_sync(0xFFFFFFFFu, sum, s);
        if (lane == 0) inv[qi] = 1.0f / sum;
    }
    __syncthreads();

    // AV with f32x2
    {
        int d4 = (tid & 15) * 4;
        unsigned long long acc01 = 0ull, acc23 = 0ull;
        const float* vb = v + (size_t)(b * SEQ) * EMB + h * HDIM + d4;
        const float* lr = lg + qq * LSTR;
        for (int t = 0; t < SEQ; t++) {
            unsigned long long wp = pack2(lr[t]);
            ulonglong2 vp = *(const ulonglong2*)(vb + (size_t)t * EMB);
            fma2(acc01, wp, vp.x);
            fma2(acc23, wp, vp.y);
        }
        int s = qt * QT + qq;
        if (s < SEQ) {
            float iv = inv[qq];
            float2 v01 = unpack2(acc01);
            float2 v23 = unpack2(acc23);
            float4 accv = make_float4(v01.x * iv, v01.y * iv, v23.x * iv, v23.y * iv);
            *(float4*)(o + (size_t)(b * SEQ + s) * EMB + h * HDIM + d4) = accv;
        }
    }
}

// ---------------------------------------------------------------------------
// LayerNorm (optional residual)
// ---------------------------------------------------------------------------
__global__ __launch_bounds__(256)
void ln_kernel(const float* __restrict__ inp, const float* __restrict__ res,
               const float* __restrict__ g, const float* __restrict__ bb,
               float* __restrict__ out, int rows) {
    int r = blockIdx.x;
    if (r >= rows) return;
    int tid = threadIdx.x;
    const float* ip = inp + (size_t)r * EMB;
    const float* rp = res ? res + (size_t)r * EMB : nullptr;
    float v[3];
    float s = 0.f;
    #pragma unroll
    for (int i = 0; i < 3; i++) {
        int c = tid + i * 256;
        float x = ip[c];
        if (rp) x += rp[c];
        v[i] = x;
        s += x;
    }
    __shared__ float sh[256];
    sh[tid] = s; __syncthreads();
    for (int st = 128; st > 0; st >>= 1) { if (tid < st) sh[tid] += sh[tid + st]; __syncthreads(); }
    float mean = sh[0] * (1.f / EMB);
    __syncthreads();
    float s2 = 0.f;
    #pragma unroll
    for (int i = 0; i < 3; i++) { float d = v[i] - mean; s2 += d * d; }
    sh[tid] = s2; __syncthreads();
    for (int st = 128; st > 0; st >>= 1) { if (tid < st) sh[tid] += sh[tid + st]; __syncthreads(); }
    float rstd = rsqrtf(sh[0] * (1.f / EMB) + 1e-5f);
    #pragma unroll
    for (int i = 0; i < 3; i++) {
        int c = tid + i * 256;
        out[(size_t)r * EMB + c] = (v[i] - mean) * rstd * g[c] + bb[c];
    }
}

// ---------------------------------------------------------------------------
// Classifier
// ---------------------------------------------------------------------------
__global__ void clf_kernel(const float* __restrict__ x, const float* __restrict__ w,
                           const float* __restrict__ b, float* __restrict__ out) {
    int idx = threadIdx.x;
    if (idx >= BATCH * 2) return;
    int bb = idx / 2, c = idx % 2;
    const float* xr = x + (size_t)bb * SEQ * EMB;
    float acc = b[c];
    for (int e = 0; e < EMB; e++) acc += xr[e] * w[e * 2 + c];
    out[idx] = acc;
}

// ---------------------------------------------------------------------------
// Host orchestration
// ---------------------------------------------------------------------------
static inline void run_gemm(const float* A, const float* B, const float* bias,
                            float* C, int M, int N, int K, int act) {
    dim3 grid(N / BN, (M + BM - 1) / BM);
    gemm_kernel<<<grid, 256>>>(A, B, bias, C, M, N, K, act);
}

extern "C" void kernel_launch(void* const* d_in, const int* in_sizes, int n_in,
                              void* d_out, int out_size) {
    const float* img     = (const float*)d_in[0];
    const float* patch_w = (const float*)d_in[1];
    const float* patch_b = (const float*)d_in[2];
    const float* cls_tok = (const float*)d_in[3];
    const float* Wq      = (const float*)d_in[4];
    const float* Wk      = (const float*)d_in[5];
    const float* Wv      = (const float*)d_in[6];
    const float* Wo      = (const float*)d_in[7];
    const float* bo      = (const float*)d_in[8];
    const float* ln1_g   = (const float*)d_in[9];
    const float* ln1_b   = (const float*)d_in[10];
    const float* fln_g   = (const float*)d_in[11];
    const float* fln_b   = (const float*)d_in[12];
    const float* fc1_w   = (const float*)d_in[13];
    const float* fc1_b   = (const float*)d_in[14];
    const float* fc2_w   = (const float*)d_in[15];
    const float* fc2_b   = (const float*)d_in[16];
    const float* ln2_g   = (const float*)d_in[17];
    const float* ln2_b   = (const float*)d_in[18];
    const float* clf_w   = (const float*)d_in[19];
    const float* clf_b   = (const float*)d_in[20];
    float* out = (float*)d_out;

    cudaFuncSetAttribute(attn_kernel, cudaFuncAttributeMaxDynamicSharedMemorySize, ATT_SMEM);

    float *x, *q, *k, *v, *o, *t1, *t2, *pos;
    cudaGetSymbolAddress((void**)&x,   g_x);
    cudaGetSymbolAddress((void**)&q,   g_q);
    cudaGetSymbolAddress((void**)&k,   g_k);
    cudaGetSymbolAddress((void**)&v,   g_v);
    cudaGetSymbolAddress((void**)&o,   g_o);
    cudaGetSymbolAddress((void**)&t1,  g_t1);
    cudaGetSymbolAddress((void**)&t2,  g_t2);
    cudaGetSymbolAddress((void**)&pos, g_pos);

    // --- Embedding ---
    patchify_kernel<<<(PROWS * EMB + 255) / 256, 256>>>(img, t1);
    pos_kernel<<<(SEQ * EMB + 255) / 256, 256>>>(pos);
    run_gemm(t1, patch_w, patch_b, t2, PROWS, EMB, EMB, 0);
    assemble_kernel<<<(ROWS * EMB + 255) / 256, 256>>>(t2, cls_tok, pos, x);

    const int MB = (ROWS + BM - 1) / BM;   // 50

    // --- Transformer layers ---
    for (int l = 0; l < LAYERS; l++) {
        const float* wq = Wq + (size_t)l * EMB * EMB;
        const float* wk = Wk + (size_t)l * EMB * EMB;
        const float* wv = Wv + (size_t)l * EMB * EMB;
        const float* wo = Wo + (size_t)l * EMB * EMB;
        const float* w1 = fc1_w + (size_t)l * EMB * FFN;
        const float* w2 = fc2_w + (size_t)l * FFN * EMB;

        // merged QKV (one 900-block launch)
        qkv_kernel<<<dim3(18, MB), 256>>>(x, wq, wk, wv, q, k, v, ROWS);

        dim3 agrid((SEQ + QT - 1) / QT, HEADS, BATCH);
        attn_kernel<<<agrid, 256, ATT_SMEM>>>(q, k, v, o);

        run_gemm(o, wo, bo + l * EMB, t2, ROWS, EMB, EMB, 0);
        ln_kernel<<<ROWS, 256>>>(t2, x, ln1_g + l * EMB, ln1_b + l * EMB, x, ROWS);

        ln_kernel<<<ROWS, 256>>>(x, nullptr, fln_g + l * EMB, fln_b + l * EMB, t2, ROWS);
        run_gemm(t2, w1, fc1_b + l * FFN, t1, ROWS, FFN, EMB, 1);
        run_gemm(t1, w2, fc2_b + l * EMB, t2, ROWS, EMB, FFN, 0);
        ln_kernel<<<ROWS, 256>>>(t2, x, ln2_g + l * EMB, ln2_b + l * EMB, x, ROWS);
    }

    // --- Classifier head ---
    clf_kernel<<<1, 64>>>(x, clf_w, clf_b, out);
}

// round 13
// speedup vs baseline: 2.0370x; 2.0370x over previous
#include <cuda_runtime.h>
#include <math.h>
#include <stdint.h>

// ---------------------------------------------------------------------------
// ViT-Base forward: B=32, S=197, E=768, H=12, D=64, FC=3072, L=12
// Round 12: restore proven R9 configuration (27.2ms) with ONE safe change:
//   B tile loaded via cp.async (no reg staging / no STS for B).
//   A path, mainloop body, attention, LN all byte-equivalent to R9.
// ---------------------------------------------------------------------------

#define BATCH 32
#define SEQ   197
#define EMB   768
#define HEADS 12
#define HDIM  64
#define FFN   3072
#define LAYERS 12
#define NPATCH 196
#define ROWS  (BATCH * SEQ)      // 6304
#define PROWS (BATCH * NPATCH)   // 6272

// Scratch
__device__ float g_x  [ROWS * EMB];
__device__ float g_q  [ROWS * EMB];
__device__ float g_k  [ROWS * EMB];
__device__ float g_v  [ROWS * EMB];
__device__ float g_o  [ROWS * EMB];
__device__ float g_t2 [ROWS * EMB];
__device__ float g_t1 [ROWS * FFN];
__device__ float g_pos[SEQ * EMB];

// ---------------------------------------------------------------------------
// Packed f32x2 helpers
// ---------------------------------------------------------------------------
__device__ __forceinline__ void fma2(unsigned long long& acc, unsigned long long a,
                                     unsigned long long b) {
    asm("fma.rn.f32x2 %0, %1, %2, %0;" : "+l"(acc) : "l"(a), "l"(b));
}
__device__ __forceinline__ unsigned long long pack2(float x) {
    unsigned long long r;
    asm("mov.b64 %0, {%1, %1};" : "=l"(r) : "f"(x));
    return r;
}
__device__ __forceinline__ float2 unpack2(unsigned long long v) {
    float2 f;
    asm("mov.b64 {%0, %1}, %2;" : "=f"(f.x), "=f"(f.y) : "l"(v));
    return f;
}
__device__ __forceinline__ float gelu(float v) {
    return 0.5f * v * (1.f + erff(v * 0.70710678118654752f));
}
__device__ __forceinline__ unsigned su32(const void* p) {
    return (unsigned)__cvta_generic_to_shared(p);
}
__device__ __forceinline__ void cp16(float* dst, const float* src) {
    asm volatile("cp.async.cg.shared.global [%0], [%1], 16;\n"
                 :: "r"(su32(dst)), "l"(src));
}
#define CP_COMMIT() asm volatile("cp.async.commit_group;\n")
template<int N> __device__ __forceinline__ void cp_wait() {
    asm volatile("cp.async.wait_group %0;\n" :: "n"(N));
}

// ---------------------------------------------------------------------------
// Patchify / pos / assemble
// ---------------------------------------------------------------------------
__global__ void patchify_kernel(const float* __restrict__ img, float* __restrict__ out) {
    int idx = blockIdx.x * 256 + threadIdx.x;
    if (idx >= PROWS * EMB) return;
    int col = idx % EMB;
    int row = idx / EMB;
    int b = row / NPATCH, p = row % NPATCH;
    int hh = p / 14, ww = p % 14;
    int c = col % 3;
    int pp = col / 3;
    int p1 = pp / 16, p2 = pp % 16;
    out[idx] = img[((b * 3 + c) * 224 + hh * 16 + p1) * 224 + ww * 16 + p2];
}

__global__ void pos_kernel(float* __restrict__ pos) {
    int idx = blockIdx.x * 256 + threadIdx.x;
    if (idx >= SEQ * EMB) return;
    int t = idx / EMB, j = idx % EMB;
    float val = 0.f;
    if (t > 0) {
        int tok = t - 1;
        int quad = j / 192;
        int i = j % 192;
        float omega = expf(-((float)i / 191.f) * logf(10000.f));
        float coord = (quad < 2) ? (float)(tok % 14) : (float)(tok / 14);
        float arg = coord * omega;
        val = (quad & 1) ? cosf(arg) : sinf(arg);
    }
    pos[idx] = val;
}

__global__ void assemble_kernel(const float* __restrict__ emb, const float* __restrict__ cls,
                                const float* __restrict__ pos, float* __restrict__ x) {
    int idx = blockIdx.x * 256 + threadIdx.x;
    if (idx >= ROWS * EMB) return;
    int e = idx % EMB;
    int bs = idx / EMB;
    int s = bs % SEQ, b = bs / SEQ;
    float val;
    if (s == 0) val = cls[e];
    else        val = emb[(b * NPATCH + s - 1) * EMB + e] + pos[s * EMB + e];
    x[idx] = val;
}

// ---------------------------------------------------------------------------
// f32x2 GEMM core (128x128x16 tile, 256 threads, 8x8 microtile).
// A staged via LDG->reg->STS (transposed, as in R9). B via cp.async.
// ---------------------------------------------------------------------------
#define BM 128
#define BN 128
#define BK 16
#define STG 4096   // floats per stage: A 16x128 + B 16x128

__device__ __forceinline__ void gemm_core(
    const float* __restrict__ Ab, int lda,
    const float* __restrict__ Bb, int ldb,
    int Kiter, const float* __restrict__ bias,
    float* __restrict__ Cb, int ldc, int mrem, int act, float* sm)
{
    int tid = threadIdx.x;
    int tx = tid & 15, ty = tid >> 4;

    int ar[2], ac[2], br[2], bc[2];
    float4 pa[2];
    #pragma unroll
    for (int i = 0; i < 2; i++) {
        int c = tid + i * 256;
        ar[i] = c >> 2;  ac[i] = (c & 3) * 4;
        br[i] = c >> 5;  bc[i] = (c & 31) * 4;
    }

    auto ldgA = [&](int k0) {
        #pragma unroll
        for (int i = 0; i < 2; i++) {
            if (ar[i] < mrem)
                pa[i] = *(const float4*)(Ab + (size_t)ar[i] * lda + k0 + ac[i]);
            else
                pa[i] = make_float4(0.f, 0.f, 0.f, 0.f);
        }
    };
    auto stsA = [&](int s) {
        float* as = sm + s * STG;
        #pragma unroll
        for (int i = 0; i < 2; i++) {
            as[(ac[i] + 0) * BM + ar[i]] = pa[i].x;   // transpose A -> [k][m]
            as[(ac[i] + 1) * BM + ar[i]] = pa[i].y;
            as[(ac[i] + 2) * BM + ar[i]] = pa[i].z;
            as[(ac[i] + 3) * BM + ar[i]] = pa[i].w;
        }
    };
    auto cpB = [&](int s, int k0) {
        float* bs = sm + s * STG + 2048;
        #pragma unroll
        for (int i = 0; i < 2; i++)
            cp16(bs + br[i] * BN + bc[i], Bb + (size_t)(k0 + br[i]) * ldb + bc[i]);
    };

    unsigned long long acc[8][4];
    #pragma unroll
    for (int i = 0; i < 8; i++)
        #pragma unroll
        for (int j = 0; j < 4; j++) acc[i][j] = 0ull;

    // preamble: stage 0
    ldgA(0);
    cpB(0, 0);
    CP_COMMIT();
    stsA(0);

    int nk = Kiter / BK;
    for (int kt = 0; kt < nk; kt++) {
        cp_wait<0>();        // B(kt) arrived (own thread); barrier makes it collective
        __syncthreads();     // + all A-sts(kt) visible; stage kt^1 readers retired

        if (kt + 1 < nk) {
            ldgA((kt + 1) * BK);
            cpB((kt + 1) & 1, (kt + 1) * BK);   // safe: stage (kt+1)&1 readers done
            CP_COMMIT();
        }

        const float* as = sm + (kt & 1) * STG;
        const float* bs = as + 2048;
        #pragma unroll
        for (int k = 0; k < BK; k++) {
            float4 a0 = *(const float4*)(as + k * BM + ty * 4);
            float4 a1 = *(const float4*)(as + k * BM + ty * 4 + 64);
            unsigned long long b0 = *(const unsigned long long*)(bs + k * BN + tx * 4);
            unsigned long long b1 = *(const unsigned long long*)(bs + k * BN + tx * 4 + 2);
            unsigned long long b2 = *(const unsigned long long*)(bs + k * BN + tx * 4 + 64);
            unsigned long long b3 = *(const unsigned long long*)(bs + k * BN + tx * 4 + 66);
            unsigned long long av[8];
            av[0] = pack2(a0.x); av[1] = pack2(a0.y); av[2] = pack2(a0.z); av[3] = pack2(a0.w);
            av[4] = pack2(a1.x); av[5] = pack2(a1.y); av[6] = pack2(a1.z); av[7] = pack2(a1.w);
            #pragma unroll
            for (int i = 0; i < 8; i++) {
                fma2(acc[i][0], av[i], b0);
                fma2(acc[i][1], av[i], b1);
                fma2(acc[i][2], av[i], b2);
                fma2(acc[i][3], av[i], b3);
            }
        }
        if (kt + 1 < nk) stsA((kt + 1) & 1);   // writes stage kt^1; its readers retired
    }

    #pragma unroll
    for (int i = 0; i < 8; i++) {
        int lr = ty * 4 + (i & 3) + (i >> 2) * 64;
        if (lr >= mrem) continue;
        float* crow = Cb + (size_t)lr * ldc;
        #pragma unroll
        for (int j = 0; j < 4; j++) {
            int lc = tx * 4 + (j & 1) * 2 + (j >> 1) * 64;
            float2 v = unpack2(acc[i][j]);
            if (bias) { v.x += bias[lc]; v.y += bias[lc + 1]; }
            if (act)  { v.x = gelu(v.x); v.y = gelu(v.y); }
            *(float2*)(crow + lc) = v;
        }
    }
}

// Standard GEMM: C[M,N] = A[M,K] @ B[K,N] (+bias)(+GELU)
__global__ __launch_bounds__(256, 2)
void gemm_kernel(const float* __restrict__ A, const float* __restrict__ B,
                 const float* __restrict__ bias, float* __restrict__ C,
                 int M, int N, int K, int act) {
    __shared__ float sm[2 * STG];
    int bm = blockIdx.y * BM, bn = blockIdx.x * BN;
    gemm_core(A + (size_t)bm * K, K, B + bn, N, K,
              bias ? bias + bn : nullptr,
              C + (size_t)bm * N + bn, N, M - bm, act, sm);
}

// ---------------------------------------------------------------------------
// Tiled attention (R9-verified, fp32): block = (16-query tile, head, batch).
// ---------------------------------------------------------------------------
#define QT   16
#define KSTR 68
#define LSTR 208
#define ATT_QS   (SEQ * KSTR)
#define ATT_LG   (ATT_QS + QT * KSTR)
#define ATT_INV  (ATT_LG + QT * LSTR)
#define ATT_SMEM ((ATT_INV + 16) * 4)

__global__ __launch_bounds__(256)
void attn_kernel(const float* __restrict__ q, const float* __restrict__ k,
                 const float* __restrict__ v, float* __restrict__ o) {
    extern __shared__ float sm[];
    float* Ks  = sm;
    float* Qs  = sm + ATT_QS;
    float* lg  = sm + ATT_LG;
    float* inv = sm + ATT_INV;
    int qt = blockIdx.x, h = blockIdx.y, b = blockIdx.z;
    int tid = threadIdx.x;
    const float scale = 0.125f;

    for (int idx = tid; idx < SEQ * 16; idx += 256) {
        int t = idx >> 4, d4 = (idx & 15) * 4;
        *(float4*)(Ks + t * KSTR + d4) =
            *(const float4*)(k + (size_t)(b * SEQ + t) * EMB + h * HDIM + d4);
    }
    {
        int t = tid >> 4, d4 = (tid & 15) * 4;
        int s = qt * QT + t;
        float4 qv = make_float4(0.f, 0.f, 0.f, 0.f);
        if (s < SEQ) qv = *(const float4*)(q + (size_t)(b * SEQ + s) * EMB + h * HDIM + d4);
        *(float4*)(Qs + t * KSTR + d4) = qv;
    }
    __syncthreads();

    int qq = tid >> 4, g = tid & 15;
    for (int pass = 0; pass < 13; pass++) {
        int t = g + pass * 16;
        if (t < SEQ) {
            float acc = 0.f;
            #pragma unroll
            for (int d4 = 0; d4 < HDIM; d4 += 4) {
                float4 qv = *(float4*)(Qs + qq * KSTR + d4);
                float4 kv = *(float4*)(Ks + t * KSTR + d4);
                acc += qv.x * kv.x + qv.y * kv.y + qv.z * kv.z + qv.w * kv.w;
            }
            lg[qq * LSTR + t] = acc * scale;
        }
    }
    __syncthreads();

    int warp = tid >> 5, lane = tid & 31;
    #pragma unroll
    for (int qi = warp * 2; qi < warp * 2 + 2; qi++) {
        float m = -1e30f;
        for (int t = lane; t < SEQ; t += 32) m = fmaxf(m, lg[qi * LSTR + t]);
        #pragma unroll
        for (int s = 16; s; s >>= 1) m = fmaxf(m, __shfl_xor_sync(0xFFFFFFFFu, m, s));
        float sum = 0.f;
        for (int t = lane; t < SEQ; t += 32) {
            float e = expf(lg[qi * LSTR + t] - m);
            lg[qi * LSTR + t] = e;
            sum += e;
        }
        #pragma unroll
        for (int s = 16; s; s >>= 1) sum += __shfl_xor_sync(0xFFFFFFFFu, sum, s);
        if (lane == 0) inv[qi] = 1.0f / sum;
    }
    __syncthreads();

    {
        int d4 = (tid & 15) * 4;
        float4 accv = make_float4(0.f, 0.f, 0.f, 0.f);
        const float* vb = v + (size_t)(b * SEQ) * EMB + h * HDIM + d4;
        const float* lr = lg + qq * LSTR;
        for (int t = 0; t < SEQ; t++) {
            float w = lr[t];
            float4 vv = *(const float4*)(vb + (size_t)t * EMB);
            accv.x += w * vv.x; accv.y += w * vv.y;
            accv.z += w * vv.z; accv.w += w * vv.w;
        }
        int s = qt * QT + qq;
        if (s < SEQ) {
            float iv = inv[qq];
            accv.x *= iv; accv.y *= iv; accv.z *= iv; accv.w *= iv;
            *(float4*)(o + (size_t)(b * SEQ + s) * EMB + h * HDIM + d4) = accv;
        }
    }
}

// ---------------------------------------------------------------------------
// LayerNorm (optional residual)
// ---------------------------------------------------------------------------
__global__ __launch_bounds__(256)
void ln_kernel(const float* __restrict__ inp, const float* __restrict__ res,
               const float* __restrict__ g, const float* __restrict__ bb,
               float* __restrict__ out, int rows) {
    int r = blockIdx.x;
    if (r >= rows) return;
    int tid = threadIdx.x;
    const float* ip = inp + (size_t)r * EMB;
    const float* rp = res ? res + (size_t)r * EMB : nullptr;
    float v[3];
    float s = 0.f;
    #pragma unroll
    for (int i = 0; i < 3; i++) {
        int c = tid + i * 256;
        float x = ip[c];
        if (rp) x += rp[c];
        v[i] = x;
        s += x;
    }
    __shared__ float sh[256];
    sh[tid] = s; __syncthreads();
    for (int st = 128; st > 0; st >>= 1) { if (tid < st) sh[tid] += sh[tid + st]; __syncthreads(); }
    float mean = sh[0] * (1.f / EMB);
    __syncthreads();
    float s2 = 0.f;
    #pragma unroll
    for (int i = 0; i < 3; i++) { float d = v[i] - mean; s2 += d * d; }
    sh[tid] = s2; __syncthreads();
    for (int st = 128; st > 0; st >>= 1) { if (tid < st) sh[tid] += sh[tid + st]; __syncthreads(); }
    float rstd = rsqrtf(sh[0] * (1.f / EMB) + 1e-5f);
    #pragma unroll
    for (int i = 0; i < 3; i++) {
        int c = tid + i * 256;
        out[(size_t)r * EMB + c] = (v[i] - mean) * rstd * g[c] + bb[c];
    }
}

// ---------------------------------------------------------------------------
// Classifier
// ---------------------------------------------------------------------------
__global__ void clf_kernel(const float* __restrict__ x, const float* __restrict__ w,
                           const float* __restrict__ b, float* __restrict__ out) {
    int idx = threadIdx.x;
    if (idx >= BATCH * 2) return;
    int bb = idx / 2, c = idx % 2;
    const float* xr = x + (size_t)bb * SEQ * EMB;
    float acc = b[c];
    for (int e = 0; e < EMB; e++) acc += xr[e] * w[e * 2 + c];
    out[idx] = acc;
}

// ---------------------------------------------------------------------------
// Host orchestration
// ---------------------------------------------------------------------------
static inline void run_gemm(const float* A, const float* B, const float* bias,
                            float* C, int M, int N, int K, int act) {
    dim3 grid(N / BN, (M + BM - 1) / BM);
    gemm_kernel<<<grid, 256>>>(A, B, bias, C, M, N, K, act);
}

extern "C" void kernel_launch(void* const* d_in, const int* in_sizes, int n_in,
                              void* d_out, int out_size) {
    const float* img     = (const float*)d_in[0];
    const float* patch_w = (const float*)d_in[1];
    const float* patch_b = (const float*)d_in[2];
    const float* cls_tok = (const float*)d_in[3];
    const float* Wq      = (const float*)d_in[4];
    const float* Wk      = (const float*)d_in[5];
    const float* Wv      = (const float*)d_in[6];
    const float* Wo      = (const float*)d_in[7];
    const float* bo      = (const float*)d_in[8];
    const float* ln1_g   = (const float*)d_in[9];
    const float* ln1_b   = (const float*)d_in[10];
    const float* fln_g   = (const float*)d_in[11];
    const float* fln_b   = (const float*)d_in[12];
    const float* fc1_w   = (const float*)d_in[13];
    const float* fc1_b   = (const float*)d_in[14];
    const float* fc2_w   = (const float*)d_in[15];
    const float* fc2_b   = (const float*)d_in[16];
    const float* ln2_g   = (const float*)d_in[17];
    const float* ln2_b   = (const float*)d_in[18];
    const float* clf_w   = (const float*)d_in[19];
    const float* clf_b   = (const float*)d_in[20];
    float* out = (float*)d_out;

    cudaFuncSetAttribute(attn_kernel, cudaFuncAttributeMaxDynamicSharedMemorySize, ATT_SMEM);

    float *x, *q, *k, *v, *o, *t1, *t2, *pos;
    cudaGetSymbolAddress((void**)&x,   g_x);
    cudaGetSymbolAddress((void**)&q,   g_q);
    cudaGetSymbolAddress((void**)&k,   g_k);
    cudaGetSymbolAddress((void**)&v,   g_v);
    cudaGetSymbolAddress((void**)&o,   g_o);
    cudaGetSymbolAddress((void**)&t1,  g_t1);
    cudaGetSymbolAddress((void**)&t2,  g_t2);
    cudaGetSymbolAddress((void**)&pos, g_pos);

    // --- Embedding ---
    patchify_kernel<<<(PROWS * EMB + 255) / 256, 256>>>(img, t1);
    pos_kernel<<<(SEQ * EMB + 255) / 256, 256>>>(pos);
    run_gemm(t1, patch_w, patch_b, t2, PROWS, EMB, EMB, 0);
    assemble_kernel<<<(ROWS * EMB + 255) / 256, 256>>>(t2, cls_tok, pos, x);

    // --- Transformer layers ---
    for (int l = 0; l < LAYERS; l++) {
        const float* wq = Wq + (size_t)l * EMB * EMB;
        const float* wk = Wk + (size_t)l * EMB * EMB;
        const float* wv = Wv + (size_t)l * EMB * EMB;
        const float* wo = Wo + (size_t)l * EMB * EMB;
        const float* w1 = fc1_w + (size_t)l * EMB * FFN;
        const float* w2 = fc2_w + (size_t)l * FFN * EMB;

        run_gemm(x, wq, nullptr, q, ROWS, EMB, EMB, 0);
        run_gemm(x, wk, nullptr, k, ROWS, EMB, EMB, 0);
        run_gemm(x, wv, nullptr, v, ROWS, EMB, EMB, 0);

        dim3 agrid((SEQ + QT - 1) / QT, HEADS, BATCH);
        attn_kernel<<<agrid, 256, ATT_SMEM>>>(q, k, v, o);

        run_gemm(o, wo, bo + l * EMB, t2, ROWS, EMB, EMB, 0);
        ln_kernel<<<ROWS, 256>>>(t2, x, ln1_g + l * EMB, ln1_b + l * EMB, x, ROWS);

        ln_kernel<<<ROWS, 256>>>(x, nullptr, fln_g + l * EMB, fln_b + l * EMB, t2, ROWS);
        run_gemm(t2, w1, fc1_b + l * FFN, t1, ROWS, FFN, EMB, 1);
        run_gemm(t1, w2, fc2_b + l * EMB, t2, ROWS, EMB, FFN, 0);
        ln_kernel<<<ROWS, 256>>>(t2, x, ln2_g + l * EMB, ln2_b + l * EMB, x, ROWS);
    }

    // --- Classifier head ---
    clf_kernel<<<1, 64>>>(x, clf_w, clf_b, out);
}